// round 8
// baseline (speedup 1.0000x reference)
#include <cuda_runtime.h>
#include <cuda_fp16.h>
#include <cstdint>

#define N_NODES 65536
#define N_EDGES 1048576
#define FEAT    64
#define NB2     512          // fused kernel grid (co-resident: 512 <= 4*148)

// ------------------------- device scratch (no allocs) -----------------------
__device__ __align__(16) __half g_support_h[(size_t)N_NODES * FEAT]; // 8 MB
__device__ __align__(16) int   g_cnt[N_NODES];   // zero-init; self-cleaned per run
__device__ __align__(16) int   g_rs[N_NODES + 4];
__device__ __align__(16) int   g_cur[N_NODES];
__device__ __align__(16) int   g_bsum[64];
__device__ __align__(16) int2  g_epair[N_EDGES];
__device__ unsigned g_barcnt;
__device__ unsigned g_bargen;

// ---- packed f32x2 helpers ---------------------------------------------------
__device__ __forceinline__ unsigned long long pk2(float x, float y) {
    unsigned long long r;
    asm("mov.b64 %0, {%1, %2};" : "=l"(r) : "f"(x), "f"(y));
    return r;
}
__device__ __forceinline__ void fma2(unsigned long long& d,
                                     unsigned long long a, unsigned long long b) {
    asm("fma.rn.f32x2 %0, %1, %2, %0;" : "+l"(d) : "l"(a), "l"(b));
}
__device__ __forceinline__ float2 up2(unsigned long long v) {
    float2 f;
    asm("mov.b64 {%0, %1}, %2;" : "=f"(f.x), "=f"(f.y) : "l"(v));
    return f;
}

// ---------------------------------------------------------------------------
// Kernel 1: GEMM tile (64 rows) + edge-row histogram chunk (1024 edges).
// ---------------------------------------------------------------------------
__global__ __launch_bounds__(256) void gemm_hist(const float* __restrict__ X,
                                                 const float* __restrict__ W,
                                                 const int4*  __restrict__ erow4) {
    __shared__ float4 Ws[64][16];
    __shared__ float4 Xs[64][16];

    const int tid  = threadIdx.x;
    const int base = blockIdx.x * 64;

    const float4* X4 = (const float4*)(X + (size_t)base * FEAT);
    const float4* W4 = (const float4*)W;
    float4* XsF = (float4*)Xs;
    float4* WsF = (float4*)Ws;
#pragma unroll
    for (int i = 0; i < 4; i++) {
        const int idx = tid + i * 256;
        XsF[idx] = X4[idx];
        WsF[idx] = W4[idx];
    }

    // histogram chunk: atomics drain under the GEMM FMA chains
    const int4 r = erow4[blockIdx.x * 256 + tid];
    atomicAdd(&g_cnt[r.x], 1);
    atomicAdd(&g_cnt[r.y], 1);
    atomicAdd(&g_cnt[r.z], 1);
    atomicAdd(&g_cnt[r.w], 1);

    __syncthreads();

    const int rt = tid >> 4;
    const int ct = tid & 15;

    unsigned long long acc[4][2];
#pragma unroll
    for (int i = 0; i < 4; i++) { acc[i][0] = pk2(0.f, 0.f); acc[i][1] = pk2(0.f, 0.f); }

#pragma unroll
    for (int kk = 0; kk < 16; kk++) {
        const float4 w0 = Ws[kk * 4 + 0][ct];
        const float4 w1 = Ws[kk * 4 + 1][ct];
        const float4 w2 = Ws[kk * 4 + 2][ct];
        const float4 w3 = Ws[kk * 4 + 3][ct];
        const unsigned long long wp00 = pk2(w0.x, w0.y), wp01 = pk2(w0.z, w0.w);
        const unsigned long long wp10 = pk2(w1.x, w1.y), wp11 = pk2(w1.z, w1.w);
        const unsigned long long wp20 = pk2(w2.x, w2.y), wp21 = pk2(w2.z, w2.w);
        const unsigned long long wp30 = pk2(w3.x, w3.y), wp31 = pk2(w3.z, w3.w);
#pragma unroll
        for (int i = 0; i < 4; i++) {
            const float4 x = Xs[rt + 16 * i][kk];
            unsigned long long xx;
            xx = pk2(x.x, x.x); fma2(acc[i][0], xx, wp00); fma2(acc[i][1], xx, wp01);
            xx = pk2(x.y, x.y); fma2(acc[i][0], xx, wp10); fma2(acc[i][1], xx, wp11);
            xx = pk2(x.z, x.z); fma2(acc[i][0], xx, wp20); fma2(acc[i][1], xx, wp21);
            xx = pk2(x.w, x.w); fma2(acc[i][0], xx, wp30); fma2(acc[i][1], xx, wp31);
        }
    }

#pragma unroll
    for (int i = 0; i < 4; i++) {
        const int row = base + rt + 16 * i;
        const float2 a = up2(acc[i][0]);
        const float2 b = up2(acc[i][1]);
        const __half2 ha = __floats2half2_rn(a.x, a.y);
        const __half2 hb = __floats2half2_rn(b.x, b.y);
        uint2 st;
        st.x = *(const unsigned*)&ha;
        st.y = *(const unsigned*)&hb;
        *(uint2*)(g_support_h + (size_t)row * FEAT + ct * 4) = st;
    }
}

// ---- device-wide barrier across NB2 co-resident blocks ----------------------
__device__ __forceinline__ void gbar512() {
    __syncthreads();
    if (threadIdx.x == 0) {
        __threadfence();
        const unsigned gen = *(volatile unsigned*)&g_bargen;
        if (atomicAdd(&g_barcnt, 1u) == NB2 - 1u) {
            g_barcnt = 0;
            __threadfence();
            *(volatile unsigned*)&g_bargen = gen + 1u;
        } else {
            while (*(volatile unsigned*)&g_bargen == gen) { __nanosleep(32); }
        }
    }
    __syncthreads();
}

// ---------------------------------------------------------------------------
// Kernel 2 (fused): CSR scan -> reorder -> SpMM+bias+ReLU
// 512 blocks x 256 threads, all co-resident (regs capped 64; all phases light).
// ---------------------------------------------------------------------------
__global__ __launch_bounds__(256, 4) void csr_spmm(
    const int4*   __restrict__ erow4,
    const int4*   __restrict__ ecol4,
    const float4* __restrict__ eval4,
    const float*  __restrict__ bias,
    float*        __restrict__ out)
{
    __shared__ int wsum[8];
    const int tid = threadIdx.x;
    const int bid = blockIdx.x;

    // ================= P1: per-block scan of counts (blocks 0..63) =========
    int4 cnt4;
    int  ex = 0;
    if (bid < 64) {
        const int i = bid * 256 + tid;
        cnt4 = ((const int4*)g_cnt)[i];
        const int s = cnt4.x + cnt4.y + cnt4.z + cnt4.w;

        const int lane = tid & 31, wid = tid >> 5;
        int x = s;
#pragma unroll
        for (int d = 1; d < 32; d <<= 1) {
            const int y = __shfl_up_sync(0xFFFFFFFFu, x, d);
            if (lane >= d) x += y;
        }
        if (lane == 31) wsum[wid] = x;
        __syncthreads();
        if (wid == 0) {
            int w = (lane < 8) ? wsum[lane] : 0;
#pragma unroll
            for (int d = 1; d < 8; d <<= 1) {
                const int y = __shfl_up_sync(0xFFFFFFFFu, w, d);
                if (lane >= d) w += y;
            }
            if (lane < 8) wsum[lane] = w;
        }
        __syncthreads();
        const int incl = x + (wid > 0 ? wsum[wid - 1] : 0);
        ex = incl - s;
        if (tid == 255) g_bsum[bid] = incl;
    }
    gbar512();

    // ================= P2: block 0 scans the 64 block sums ==================
    if (bid == 0 && tid < 32) {
        const int a = __ldcg(&g_bsum[tid]);
        const int b = __ldcg(&g_bsum[tid + 32]);
        int ia = a, ib = b;
#pragma unroll
        for (int d = 1; d < 32; d <<= 1) {
            const int ya = __shfl_up_sync(0xFFFFFFFFu, ia, d);
            const int yb = __shfl_up_sync(0xFFFFFFFFu, ib, d);
            if (tid >= d) { ia += ya; ib += yb; }
        }
        const int lowtot = __shfl_sync(0xFFFFFFFFu, ia, 31);
        g_bsum[tid]      = ia - a;
        g_bsum[tid + 32] = lowtot + ib - b;
    }
    gbar512();

    // ================= P3: write row starts + cursors, clean counts =========
    if (bid < 64) {
        const int i = bid * 256 + tid;
        const int off = __ldcg(&g_bsum[bid]) + ex;
        const int4 rs = make_int4(off, off + cnt4.x, off + cnt4.x + cnt4.y,
                                  off + cnt4.x + cnt4.y + cnt4.z);
        ((int4*)g_rs)[i]  = rs;
        ((int4*)g_cur)[i] = rs;
        ((int4*)g_cnt)[i] = make_int4(0, 0, 0, 0);
        if (i == 0) g_rs[N_NODES] = N_EDGES;
    }
    gbar512();

    // ================= P4: reorder edges into CSR pairs (all 512 blocks) ====
#pragma unroll
    for (int p = 0; p < 2; p++) {
        const int i = bid * 512 + p * 256 + tid;     // int4 index over 256K
        const int4   r = erow4[i];
        const int4   c = ecol4[i];
        const float4 v = eval4[i];
        int pos;
        pos = atomicAdd(&g_cur[r.x], 1); g_epair[pos] = make_int2(c.x, __float_as_int(v.x));
        pos = atomicAdd(&g_cur[r.y], 1); g_epair[pos] = make_int2(c.y, __float_as_int(v.y));
        pos = atomicAdd(&g_cur[r.z], 1); g_epair[pos] = make_int2(c.z, __float_as_int(v.z));
        pos = atomicAdd(&g_cur[r.w], 1); g_epair[pos] = make_int2(c.w, __float_as_int(v.w));
    }
    gbar512();

    // ================= P5: SpMM + bias + ReLU, ROW PER WARP =================
    // 4096 warps x 16 rows each; lane handles features [2*lane, 2*lane+1].
    {
        const int lane = tid & 31;
        const int gw   = bid * 8 + (tid >> 5);       // global warp id 0..4095
        const float2 bb = ((const float2*)bias)[lane];
        const __half* supp = g_support_h;

        for (int rr = 0; rr < 16; rr++) {
            const int r = gw * 16 + rr;
            int i = __ldcg(&g_rs[r]);
            const int e = __ldcg(&g_rs[r + 1]);

            float ax = 0.f, ay = 0.f;
            for (; i + 4 <= e; i += 4) {
                const int2 p0 = __ldcg(&g_epair[i + 0]);
                const int2 p1 = __ldcg(&g_epair[i + 1]);
                const int2 p2 = __ldcg(&g_epair[i + 2]);
                const int2 p3 = __ldcg(&g_epair[i + 3]);
                const __half2 h0 = *(const __half2*)(supp + ((size_t)p0.x << 6) + lane * 2);
                const __half2 h1 = *(const __half2*)(supp + ((size_t)p1.x << 6) + lane * 2);
                const __half2 h2 = *(const __half2*)(supp + ((size_t)p2.x << 6) + lane * 2);
                const __half2 h3 = *(const __half2*)(supp + ((size_t)p3.x << 6) + lane * 2);
                float2 f;
                float v;
                v = __int_as_float(p0.y); f = __half22float2(h0); ax += v * f.x; ay += v * f.y;
                v = __int_as_float(p1.y); f = __half22float2(h1); ax += v * f.x; ay += v * f.y;
                v = __int_as_float(p2.y); f = __half22float2(h2); ax += v * f.x; ay += v * f.y;
                v = __int_as_float(p3.y); f = __half22float2(h3); ax += v * f.x; ay += v * f.y;
            }
            for (; i < e; i++) {
                const int2 p0 = __ldcg(&g_epair[i]);
                const __half2 h0 = *(const __half2*)(supp + ((size_t)p0.x << 6) + lane * 2);
                const float v = __int_as_float(p0.y);
                const float2 f = __half22float2(h0);
                ax += v * f.x; ay += v * f.y;
            }

            float2 o;
            o.x = fmaxf(ax + bb.x, 0.f);
            o.y = fmaxf(ay + bb.y, 0.f);
            *(float2*)(out + ((size_t)r << 6) + lane * 2) = o;
        }
    }
}

// ---------------------------------------------------------------------------
extern "C" void kernel_launch(void* const* d_in, const int* in_sizes, int n_in,
                              void* d_out, int out_size) {
    const float* X    = (const float*)d_in[0];
    const int*   erow = (const int*)  d_in[1];
    const int*   ecol = (const int*)  d_in[2];
    const float* eval = (const float*)d_in[3];
    const float* W    = (const float*)d_in[4];
    const float* bias = (const float*)d_in[5];
    float* out = (float*)d_out;

    gemm_hist<<<N_NODES / 64, 256>>>(X, W, (const int4*)erow);
    csr_spmm<<<NB2, 256>>>((const int4*)erow, (const int4*)ecol,
                           (const float4*)eval, bias, out);
}

// round 11
// speedup vs baseline: 1.3173x; 1.3173x over previous
#include <cuda_runtime.h>
#include <cuda_fp16.h>
#include <cstdint>

#define N_NODES 65536
#define N_EDGES 1048576
#define FEAT    64

// ------------------------- device scratch (no allocs) -----------------------
__device__ __align__(16) __half g_support_h[(size_t)N_NODES * FEAT]; // 8 MB
__device__ __align__(16) int   g_cnt[N_NODES];   // zero-init; self-cleaned per run
__device__ __align__(16) int   g_rs[N_NODES + 4];
__device__ __align__(16) int   g_cur[N_NODES];
__device__ __align__(16) int   g_bsum[64];
__device__ __align__(16) int2  g_epair[N_EDGES];
__device__ unsigned g_barcnt;
__device__ unsigned g_bargen;

// ---- packed f32x2 helpers ---------------------------------------------------
__device__ __forceinline__ unsigned long long pk2(float x, float y) {
    unsigned long long r;
    asm("mov.b64 %0, {%1, %2};" : "=l"(r) : "f"(x), "f"(y));
    return r;
}
__device__ __forceinline__ void fma2(unsigned long long& d,
                                     unsigned long long a, unsigned long long b) {
    asm("fma.rn.f32x2 %0, %1, %2, %0;" : "+l"(d) : "l"(a), "l"(b));
}
__device__ __forceinline__ float2 up2(unsigned long long v) {
    float2 f;
    asm("mov.b64 {%0, %1}, %2;" : "=f"(f.x), "=f"(f.y) : "l"(v));
    return f;
}

// ---------------------------------------------------------------------------
// Kernel 1: GEMM tile (64 rows) + edge-row histogram chunk (1024 edges).
// Hist atomics drain in the shadow of the FMA chains.
// ---------------------------------------------------------------------------
__global__ __launch_bounds__(256) void gemm_hist(const float* __restrict__ X,
                                                 const float* __restrict__ W,
                                                 const int4*  __restrict__ erow4) {
    __shared__ float4 Ws[64][16];
    __shared__ float4 Xs[64][16];

    const int tid  = threadIdx.x;
    const int base = blockIdx.x * 64;

    const float4* X4 = (const float4*)(X + (size_t)base * FEAT);
    const float4* W4 = (const float4*)W;
    float4* XsF = (float4*)Xs;
    float4* WsF = (float4*)Ws;
#pragma unroll
    for (int i = 0; i < 4; i++) {
        const int idx = tid + i * 256;
        XsF[idx] = X4[idx];
        WsF[idx] = W4[idx];
    }

    const int4 r = erow4[blockIdx.x * 256 + tid];
    atomicAdd(&g_cnt[r.x], 1);
    atomicAdd(&g_cnt[r.y], 1);
    atomicAdd(&g_cnt[r.z], 1);
    atomicAdd(&g_cnt[r.w], 1);

    __syncthreads();

    const int rt = tid >> 4;
    const int ct = tid & 15;

    unsigned long long acc[4][2];
#pragma unroll
    for (int i = 0; i < 4; i++) { acc[i][0] = pk2(0.f, 0.f); acc[i][1] = pk2(0.f, 0.f); }

#pragma unroll
    for (int kk = 0; kk < 16; kk++) {
        const float4 w0 = Ws[kk * 4 + 0][ct];
        const float4 w1 = Ws[kk * 4 + 1][ct];
        const float4 w2 = Ws[kk * 4 + 2][ct];
        const float4 w3 = Ws[kk * 4 + 3][ct];
        const unsigned long long wp00 = pk2(w0.x, w0.y), wp01 = pk2(w0.z, w0.w);
        const unsigned long long wp10 = pk2(w1.x, w1.y), wp11 = pk2(w1.z, w1.w);
        const unsigned long long wp20 = pk2(w2.x, w2.y), wp21 = pk2(w2.z, w2.w);
        const unsigned long long wp30 = pk2(w3.x, w3.y), wp31 = pk2(w3.z, w3.w);
#pragma unroll
        for (int i = 0; i < 4; i++) {
            const float4 x = Xs[rt + 16 * i][kk];
            unsigned long long xx;
            xx = pk2(x.x, x.x); fma2(acc[i][0], xx, wp00); fma2(acc[i][1], xx, wp01);
            xx = pk2(x.y, x.y); fma2(acc[i][0], xx, wp10); fma2(acc[i][1], xx, wp11);
            xx = pk2(x.z, x.z); fma2(acc[i][0], xx, wp20); fma2(acc[i][1], xx, wp21);
            xx = pk2(x.w, x.w); fma2(acc[i][0], xx, wp30); fma2(acc[i][1], xx, wp31);
        }
    }

#pragma unroll
    for (int i = 0; i < 4; i++) {
        const int row = base + rt + 16 * i;
        const float2 a = up2(acc[i][0]);
        const float2 b = up2(acc[i][1]);
        const __half2 ha = __floats2half2_rn(a.x, a.y);
        const __half2 hb = __floats2half2_rn(b.x, b.y);
        uint2 st;
        st.x = *(const unsigned*)&ha;
        st.y = *(const unsigned*)&hb;
        *(uint2*)(g_support_h + (size_t)row * FEAT + ct * 4) = st;
    }
}

// ---------------------------------------------------------------------------
// Kernel 2: full CSR scan (64 blocks, internal grid barrier). Self-cleans cnt.
// ---------------------------------------------------------------------------
__device__ __forceinline__ void gbar64() {
    __syncthreads();
    if (threadIdx.x == 0) {
        __threadfence();
        const unsigned gen = *(volatile unsigned*)&g_bargen;
        if (atomicAdd(&g_barcnt, 1u) == 63u) {
            g_barcnt = 0;
            __threadfence();
            *(volatile unsigned*)&g_bargen = gen + 1u;
        } else {
            while (*(volatile unsigned*)&g_bargen == gen) { __nanosleep(32); }
        }
    }
    __syncthreads();
}

__global__ __launch_bounds__(256) void scan_fused() {
    __shared__ int wsum[8];
    const int tid = threadIdx.x;
    const int bid = blockIdx.x;
    const int i = bid * 256 + tid;

    const int4 c = ((const int4*)g_cnt)[i];
    const int s = c.x + c.y + c.z + c.w;

    const int lane = tid & 31, wid = tid >> 5;
    int x = s;
#pragma unroll
    for (int d = 1; d < 32; d <<= 1) {
        const int y = __shfl_up_sync(0xFFFFFFFFu, x, d);
        if (lane >= d) x += y;
    }
    if (lane == 31) wsum[wid] = x;
    __syncthreads();
    if (wid == 0) {
        int w = (lane < 8) ? wsum[lane] : 0;
#pragma unroll
        for (int d = 1; d < 8; d <<= 1) {
            const int y = __shfl_up_sync(0xFFFFFFFFu, w, d);
            if (lane >= d) w += y;
        }
        if (lane < 8) wsum[lane] = w;
    }
    __syncthreads();
    const int incl = x + (wid > 0 ? wsum[wid - 1] : 0);
    const int ex = incl - s;
    if (tid == 255) g_bsum[bid] = incl;
    gbar64();

    if (bid == 0 && tid < 32) {
        const int a = __ldcg(&g_bsum[tid]);
        const int b = __ldcg(&g_bsum[tid + 32]);
        int ia = a, ib = b;
#pragma unroll
        for (int d = 1; d < 32; d <<= 1) {
            const int ya = __shfl_up_sync(0xFFFFFFFFu, ia, d);
            const int yb = __shfl_up_sync(0xFFFFFFFFu, ib, d);
            if (tid >= d) { ia += ya; ib += yb; }
        }
        const int lowtot = __shfl_sync(0xFFFFFFFFu, ia, 31);
        g_bsum[tid]      = ia - a;
        g_bsum[tid + 32] = lowtot + ib - b;
    }
    gbar64();

    const int off = __ldcg(&g_bsum[bid]) + ex;
    const int4 rs = make_int4(off, off + c.x, off + c.x + c.y, off + c.x + c.y + c.z);
    ((int4*)g_rs)[i]  = rs;
    ((int4*)g_cur)[i] = rs;
    ((int4*)g_cnt)[i] = make_int4(0, 0, 0, 0);
    if (i == 0) g_rs[N_NODES] = N_EDGES;
}

// ---------------------------------------------------------------------------
// Kernel 3: reorder edges into CSR (col, val) pairs
// ---------------------------------------------------------------------------
__global__ __launch_bounds__(256) void reorder(const int4*   __restrict__ erow4,
                                               const int4*   __restrict__ ecol4,
                                               const float4* __restrict__ eval4) {
    const unsigned i = blockIdx.x * 256u + threadIdx.x;
    const int4   r = erow4[i];
    const int4   c = ecol4[i];
    const float4 v = eval4[i];
    int p;
    p = atomicAdd(&g_cur[r.x], 1); g_epair[p] = make_int2(c.x, __float_as_int(v.x));
    p = atomicAdd(&g_cur[r.y], 1); g_epair[p] = make_int2(c.y, __float_as_int(v.y));
    p = atomicAdd(&g_cur[r.z], 1); g_epair[p] = make_int2(c.z, __float_as_int(v.z));
    p = atomicAdd(&g_cur[r.w], 1); g_epair[p] = make_int2(c.w, __float_as_int(v.w));
}

// ---------------------------------------------------------------------------
// Kernel 4: SpMM + bias + ReLU, ROW PER WARP (no trip-count divergence).
// Lane handles features [2*lane, 2*lane+1]; 8 rows per 256-thread block.
// ---------------------------------------------------------------------------
__global__ __launch_bounds__(256) void spmm_warp(float* __restrict__ out,
                                                 const float* __restrict__ bias) {
    const int lane = threadIdx.x & 31;
    const int r    = blockIdx.x * 8 + (threadIdx.x >> 5);

    int i = g_rs[r];                 // warp-uniform broadcast load
    const int e = g_rs[r + 1];

    const float2 bb = ((const float2*)bias)[lane];
    const __half* supp = g_support_h;

    float ax = 0.f, ay = 0.f;
    for (; i + 4 <= e; i += 4) {
        const int2 p0 = g_epair[i + 0];
        const int2 p1 = g_epair[i + 1];
        const int2 p2 = g_epair[i + 2];
        const int2 p3 = g_epair[i + 3];
        const __half2 h0 = *(const __half2*)(supp + ((size_t)p0.x << 6) + lane * 2);
        const __half2 h1 = *(const __half2*)(supp + ((size_t)p1.x << 6) + lane * 2);
        const __half2 h2 = *(const __half2*)(supp + ((size_t)p2.x << 6) + lane * 2);
        const __half2 h3 = *(const __half2*)(supp + ((size_t)p3.x << 6) + lane * 2);
        float2 f; float v;
        v = __int_as_float(p0.y); f = __half22float2(h0); ax += v * f.x; ay += v * f.y;
        v = __int_as_float(p1.y); f = __half22float2(h1); ax += v * f.x; ay += v * f.y;
        v = __int_as_float(p2.y); f = __half22float2(h2); ax += v * f.x; ay += v * f.y;
        v = __int_as_float(p3.y); f = __half22float2(h3); ax += v * f.x; ay += v * f.y;
    }
    for (; i < e; i++) {
        const int2 p0 = g_epair[i];
        const __half2 h0 = *(const __half2*)(supp + ((size_t)p0.x << 6) + lane * 2);
        const float v = __int_as_float(p0.y);
        const float2 f = __half22float2(h0);
        ax += v * f.x; ay += v * f.y;
    }

    float2 o;
    o.x = fmaxf(ax + bb.x, 0.f);
    o.y = fmaxf(ay + bb.y, 0.f);
    *(float2*)(out + ((size_t)r << 6) + lane * 2) = o;
}

// ---------------------------------------------------------------------------
extern "C" void kernel_launch(void* const* d_in, const int* in_sizes, int n_in,
                              void* d_out, int out_size) {
    const float* X    = (const float*)d_in[0];
    const int*   erow = (const int*)  d_in[1];
    const int*   ecol = (const int*)  d_in[2];
    const float* eval = (const float*)d_in[3];
    const float* W    = (const float*)d_in[4];
    const float* bias = (const float*)d_in[5];
    float* out = (float*)d_out;

    gemm_hist<<<N_NODES / 64, 256>>>(X, W, (const int4*)erow);
    scan_fused<<<64, 256>>>();
    reorder<<<N_EDGES / 1024, 256>>>((const int4*)erow, (const int4*)ecol,
                                     (const float4*)eval);
    spmm_warp<<<N_NODES / 8, 256>>>(out, bias);
}